// round 1
// baseline (speedup 1.0000x reference)
#include <cuda_runtime.h>

#define HH 128
#define WW 128
#define CC 512
#define MIDC 512
#define HWSZ (HH*WW)            // 16384
#define KTAPS 9
#define NANCH 12

#define LOC_OFF   0
#define CLS_OFF   786432        // 16384*48
#define ROI_OFF   1179648       // + 16384*24

// Scratch (allocation-free: __device__ globals)
__device__ float g_wT[KTAPS * CC * MIDC];   // [tap][ic][oc]  9.4 MB
__device__ float g_mid[HWSZ * MIDC];        // [p][oc] NHWC   32 MB

typedef unsigned long long ull;

__device__ __forceinline__ ull bcast2(float v){
    ull r; asm("mov.b64 %0, {%1, %1};" : "=l"(r) : "f"(v)); return r;
}
__device__ __forceinline__ void fma2(ull& d, ull a, ull b){
    asm("fma.rn.f32x2 %0, %1, %2, %0;" : "+l"(d) : "l"(a), "l"(b));
}
__device__ __forceinline__ float2 unpack2(ull v){
    float2 f; asm("mov.b64 {%0, %1}, %2;" : "=f"(f.x), "=f"(f.y) : "l"(v)); return f;
}

// ---------------------------------------------------------------------------
// Kernel 0: transpose conv1_w [oc][ic][tap] -> g_wT [tap][ic][oc]
// ---------------------------------------------------------------------------
__global__ void transpose_w_kernel(const float* __restrict__ w){
    int idx = blockIdx.x * 256 + threadIdx.x;
    if (idx >= KTAPS * CC * MIDC) return;
    int tap = idx / (CC * MIDC);
    int rem = idx % (CC * MIDC);
    int ic  = rem / MIDC;
    int oc  = rem % MIDC;
    g_wT[idx] = w[oc * (CC * KTAPS) + ic * KTAPS + tap];
}

// ---------------------------------------------------------------------------
// Kernel 1: conv3x3 (pad 1) + bias + relu, implicit GEMM over 9 shifted taps.
// Tile: 64 positions (one row segment) x 64 out-channels, K chunks of 16.
// 256 threads, 4x4 outputs/thread via packed f32x2 FMA.
// ---------------------------------------------------------------------------
__global__ void __launch_bounds__(256) conv3x3_kernel(
        const float* __restrict__ x, const float* __restrict__ bias){
    __shared__ float As[16][64];   // [ic_k][pos]
    __shared__ float Bs[16][64];   // [ic_k][oc]

    const int tid = threadIdx.x;
    const int p0  = blockIdx.x * 64;
    const int y   = p0 >> 7;       // row of the tile (tile fits in one row)
    const int xb  = p0 & 127;      // x0 of the tile (0 or 64)
    const int oc0 = blockIdx.y * 64;

    const int lk  = tid >> 4;      // 0..15  (smem row / m-group)
    const int lc  = tid & 15;      // 0..15  (smem col group / n-group)
    const int ty4 = lk * 4;        // m base for compute
    const int tx4 = lc * 4;        // n base for compute

    ull acc[2][4];
    #pragma unroll
    for (int i = 0; i < 2; i++)
        #pragma unroll
        for (int j = 0; j < 4; j++) acc[i][j] = 0ULL;

    for (int tap = 0; tap < 9; tap++){
        const int dy = tap / 3 - 1;
        const int dx = tap % 3 - 1;
        const int yy = y + dy;
        const bool rowok = (yy >= 0) && (yy < HH);
        const float* xrow = x + yy * WW;
        const float* wtap = g_wT + tap * (CC * MIDC);

        for (int ic0 = 0; ic0 < CC; ic0 += 16){
            // load As: x[ic0+lk][yy][xb + m + dx], zero-masked at image edges
            {
                const float* xp = xrow + (ic0 + lk) * HWSZ;
                #pragma unroll
                for (int j = 0; j < 4; j++){
                    int xc = xb + lc * 4 + j + dx;
                    As[lk][lc * 4 + j] =
                        (rowok && xc >= 0 && xc < WW) ? xp[xc] : 0.0f;
                }
            }
            // load Bs: wT[tap][ic0+lk][oc0 + n] (coalesced float4)
            *(float4*)&Bs[lk][lc * 4] =
                *(const float4*)&wtap[(ic0 + lk) * MIDC + oc0 + lc * 4];
            __syncthreads();

            #pragma unroll
            for (int kk = 0; kk < 16; kk++){
                float4 av = *(const float4*)&As[kk][ty4];
                float4 bv = *(const float4*)&Bs[kk][tx4];
                ull a01 = ((ull*)&av)[0];   // (m0, m1)
                ull a23 = ((ull*)&av)[1];   // (m2, m3)
                ull b;
                b = bcast2(bv.x); fma2(acc[0][0], a01, b); fma2(acc[1][0], a23, b);
                b = bcast2(bv.y); fma2(acc[0][1], a01, b); fma2(acc[1][1], a23, b);
                b = bcast2(bv.z); fma2(acc[0][2], a01, b); fma2(acc[1][2], a23, b);
                b = bcast2(bv.w); fma2(acc[0][3], a01, b); fma2(acc[1][3], a23, b);
            }
            __syncthreads();
        }
    }

    // epilogue: bias + relu -> g_mid[p][oc] (NHWC)
    float4 bb = *(const float4*)&bias[oc0 + tx4];
    #pragma unroll
    for (int i = 0; i < 2; i++){
        float2 v0 = unpack2(acc[i][0]);
        float2 v1 = unpack2(acc[i][1]);
        float2 v2 = unpack2(acc[i][2]);
        float2 v3 = unpack2(acc[i][3]);
        int m0 = ty4 + 2 * i;
        float4 r0 = make_float4(fmaxf(v0.x + bb.x, 0.f), fmaxf(v1.x + bb.y, 0.f),
                                fmaxf(v2.x + bb.z, 0.f), fmaxf(v3.x + bb.w, 0.f));
        float4 r1 = make_float4(fmaxf(v0.y + bb.x, 0.f), fmaxf(v1.y + bb.y, 0.f),
                                fmaxf(v2.y + bb.z, 0.f), fmaxf(v3.y + bb.w, 0.f));
        *(float4*)&g_mid[(p0 + m0)     * MIDC + oc0 + tx4] = r0;
        *(float4*)&g_mid[(p0 + m0 + 1) * MIDC + oc0 + tx4] = r1;
    }
}

// ---------------------------------------------------------------------------
// Kernel 2: fused 1x1 heads. Block = 4 positions x 72 outputs (48 loc + 24 cls).
// Writes directly into packed output slots:
//   loc:  out[p*48 + ch],  cls: out[CLS_OFF + p*24 + ch]
// ---------------------------------------------------------------------------
__global__ void __launch_bounds__(288) head_kernel(
        const float* __restrict__ loc_w, const float* __restrict__ loc_b,
        const float* __restrict__ score_w, const float* __restrict__ score_b,
        float* __restrict__ out){
    __shared__ float sm[4][512];
    const int tid   = threadIdx.x;
    const int pbase = blockIdx.x * 4;

    for (int i = tid; i < 4 * 512; i += 288)
        sm[i >> 9][i & 511] = g_mid[(pbase + (i >> 9)) * MIDC + (i & 511)];
    __syncthreads();

    const int pl = tid / 72;    // 0..3
    const int oc = tid % 72;    // 0..71

    const float* wrow = (oc < 48) ? (loc_w + oc * 512) : (score_w + (oc - 48) * 512);
    const float  bv   = (oc < 48) ? loc_b[oc] : score_b[oc - 48];

    float acc = 0.f;
    #pragma unroll 8
    for (int k = 0; k < 512; k += 4){
        float4 a = *(const float4*)&sm[pl][k];
        float4 w = *(const float4*)&wrow[k];
        acc = fmaf(a.x, w.x, acc);
        acc = fmaf(a.y, w.y, acc);
        acc = fmaf(a.z, w.z, acc);
        acc = fmaf(a.w, w.w, acc);
    }
    float v = acc + bv;
    const int p = pbase + pl;
    if (oc < 48) out[LOC_OFF + p * 48 + oc] = v;
    else         out[CLS_OFF + p * 24 + (oc - 48)] = v;
}

// ---------------------------------------------------------------------------
// Kernel 3: roi decode. Replicates the reference anchor quirk exactly:
// anchor k = p uses xi = p>>7 (x varies slowly), yi = p&127, while loc uses
// row-major spatial p. cx=gx, cy=gy, aw=round(ws/2), ah=round(hs/2).
// ---------------------------------------------------------------------------
__global__ void roi_kernel(float* __restrict__ out){
    int i = blockIdx.x * 256 + threadIdx.x;
    if (i >= HWSZ * NANCH) return;
    int p = i / NANCH, a = i % NANCH;
    float gx = (float)((p >> 7) * 16);
    float gy = (float)((p & 127) * 16);
    const float RAT[3] = {0.5f, 1.0f, 2.0f};
    const float SIZ[4] = {64.f, 128.f, 256.f, 512.f};
    float r = RAT[a >> 2], s = SIZ[a & 3];
    float hr = sqrtf(r);
    float aw = rintf(0.5f * ((1.0f / hr) * s));   // round half-even, like jnp.round
    float ah = rintf(0.5f * (hr * s));
    float4 l = *(const float4*)&out[LOC_OFF + i * 4];
    float4 ro;
    ro.x = l.x * aw + gx;
    ro.y = l.y * ah + gy;
    ro.z = expf(l.z) * aw;
    ro.w = expf(l.w) * ah;
    *(float4*)&out[ROI_OFF + i * 4] = ro;
}

// ---------------------------------------------------------------------------
extern "C" void kernel_launch(void* const* d_in, const int* in_sizes, int n_in,
                              void* d_out, int out_size){
    const float* x       = (const float*)d_in[0];
    const float* conv1_w = (const float*)d_in[1];
    const float* conv1_b = (const float*)d_in[2];
    const float* score_w = (const float*)d_in[3];
    const float* score_b = (const float*)d_in[4];
    const float* loc_w   = (const float*)d_in[5];
    const float* loc_b   = (const float*)d_in[6];
    float* out = (float*)d_out;

    transpose_w_kernel<<<(KTAPS * CC * MIDC + 255) / 256, 256>>>(conv1_w);

    dim3 gconv(HWSZ / 64, MIDC / 64);   // 256 x 8
    conv3x3_kernel<<<gconv, 256>>>(x, conv1_b);

    head_kernel<<<HWSZ / 4, 288>>>(loc_w, loc_b, score_w, score_b, out);

    roi_kernel<<<(HWSZ * NANCH + 255) / 256, 256>>>(out);
}

// round 3
// speedup vs baseline: 4.2443x; 4.2443x over previous
#include <cuda_runtime.h>
#include <cuda_bf16.h>

#define HH 128
#define WW 128
#define CC 512
#define HWSZ (HH*WW)
#define NANCH 12

#define LOC_OFF   0
#define CLS_OFF   786432
#define ROI_OFF   1179648

// ---------------------------------------------------------------------------
// Global scratch (allocation-free)
// ---------------------------------------------------------------------------
__device__ __align__(256) __nv_bfloat16 g_xhi[HWSZ * CC];      // x NHWC hi
__device__ __align__(256) __nv_bfloat16 g_xlo[HWSZ * CC];      // x NHWC lo
__device__ __align__(256) __nv_bfloat16 g_whi[9 * CC * CC];    // [tap][oc][ic]
__device__ __align__(256) __nv_bfloat16 g_wlo[9 * CC * CC];
__device__ __align__(256) __nv_bfloat16 g_mhi[HWSZ * CC];      // mid NHWC hi
__device__ __align__(256) __nv_bfloat16 g_mlo[HWSZ * CC];      // mid NHWC lo
__device__ __align__(256) __nv_bfloat16 g_hwhi[8 * 72 * 64];   // head W [kc][row72][64]
__device__ __align__(256) __nv_bfloat16 g_hwlo[8 * 72 * 64];

// ---------------------------------------------------------------------------
// Helpers (all plain sm_80+ PTX — legal on the non-'a' compute_103 target)
// ---------------------------------------------------------------------------
__device__ __forceinline__ unsigned smem_u32(const void* p){
    unsigned a;
    asm("{ .reg .u64 t; cvta.to.shared.u64 t, %1; cvt.u32.u64 %0, t; }" : "=r"(a) : "l"(p));
    return a;
}
#define SWZ(b) ((unsigned)(b) ^ ((((unsigned)(b)) >> 3) & 0x70u))

__device__ __forceinline__ void cp16(unsigned dst, const void* src, unsigned sz){
    asm volatile("cp.async.cg.shared.global [%0], [%1], 16, %2;"
        :: "r"(dst), "l"(src), "r"(sz) : "memory");
}
#define CP_COMMIT() asm volatile("cp.async.commit_group;" ::: "memory")
#define CP_WAIT0()  asm volatile("cp.async.wait_group 0;"  ::: "memory")
#define CP_WAIT1()  asm volatile("cp.async.wait_group 1;"  ::: "memory")

__device__ __forceinline__ void ldm4(unsigned* r, unsigned addr){
    asm volatile("ldmatrix.sync.aligned.m8n8.x4.shared.b16 {%0,%1,%2,%3}, [%4];"
        : "=r"(r[0]), "=r"(r[1]), "=r"(r[2]), "=r"(r[3]) : "r"(addr));
}
__device__ __forceinline__ void ldm2(unsigned* r, unsigned addr){
    asm volatile("ldmatrix.sync.aligned.m8n8.x2.shared.b16 {%0,%1}, [%2];"
        : "=r"(r[0]), "=r"(r[1]) : "r"(addr));
}
__device__ __forceinline__ void mma16816(float* d, const unsigned* a, const unsigned* b){
    asm volatile("mma.sync.aligned.m16n8k16.row.col.f32.bf16.bf16.f32 "
        "{%0,%1,%2,%3}, {%4,%5,%6,%7}, {%8,%9}, {%0,%1,%2,%3};"
        : "+f"(d[0]), "+f"(d[1]), "+f"(d[2]), "+f"(d[3])
        : "r"(a[0]), "r"(a[1]), "r"(a[2]), "r"(a[3]), "r"(b[0]), "r"(b[1]));
}

// ---------------------------------------------------------------------------
// Prep kernels
// ---------------------------------------------------------------------------
__global__ void prep_x_kernel(const float* __restrict__ x){
    __shared__ float tile[32][33];
    int hw0 = blockIdx.x * 32, c0 = blockIdx.y * 32;
    int tx = threadIdx.x, ty = threadIdx.y;
    #pragma unroll
    for (int i = 0; i < 32; i += 8)
        tile[ty + i][tx] = x[(size_t)(c0 + ty + i) * HWSZ + hw0 + tx];
    __syncthreads();
    #pragma unroll
    for (int i = 0; i < 32; i += 8){
        int hw = ty + i;
        float v = tile[tx][hw];
        __nv_bfloat16 hi = __float2bfloat16(v);
        float r = v - __bfloat162float(hi);
        size_t o = (size_t)(hw0 + hw) * CC + c0 + tx;
        g_xhi[o] = hi;
        g_xlo[o] = __float2bfloat16(r);
    }
}

__global__ void prep_w_kernel(const float* __restrict__ w){
    int idx = blockIdx.x * 256 + threadIdx.x;
    if (idx >= 9 * CC * CC) return;
    int tap = idx / (CC * CC);
    int rem = idx % (CC * CC);
    int oc  = rem >> 9;
    int ic  = rem & 511;
    float v = w[(size_t)oc * (CC * 9) + ic * 9 + tap];
    __nv_bfloat16 hi = __float2bfloat16(v);
    g_whi[idx] = hi;
    g_wlo[idx] = __float2bfloat16(v - __bfloat162float(hi));
}

__global__ void prep_hw_kernel(const float* __restrict__ loc_w,
                               const float* __restrict__ score_w){
    int idx = blockIdx.x * 256 + threadIdx.x;
    if (idx >= 8 * 72 * 64) return;
    int kc  = idx / (72 * 64);
    int rem = idx % (72 * 64);
    int row = rem >> 6;
    int k   = rem & 63;
    float v = (row < 48) ? loc_w[row * CC + kc * 64 + k]
                         : score_w[(row - 48) * CC + kc * 64 + k];
    __nv_bfloat16 hi = __float2bfloat16(v);
    g_hwhi[idx] = hi;
    g_hwlo[idx] = __float2bfloat16(v - __bfloat162float(hi));
}

// ---------------------------------------------------------------------------
// Conv 3x3 via mma.sync bf16 hi/lo (3-pass). grid(128 rows, 4 oc-groups), 256 thr.
// CTA tile: M=128 positions x N=128 oc, K = 9 taps x 512 ic, chunks of 64.
// Stage: Ah16K Al16K Bh16K Bl16K = 64KB, double-buffered = 128KB.
// ---------------------------------------------------------------------------
#define CSTG  65536
#define CDYN  (2*CSTG)

__device__ __forceinline__ void conv_load_chunk(unsigned sb, int i, int s,
                                                int y, int oc0, int tid){
    const int tap = i >> 3;
    const int ic0 = (i & 7) << 6;
    const int dy = tap / 3 - 1, dx = tap % 3 - 1;
    const int yy = y + dy;
    const bool rowok = ((unsigned)yy < 128u);
    const unsigned stg = sb + s * CSTG;
    #pragma unroll
    for (int j = 0; j < 8; j++){
        int id = tid + j * 256;
        int part = id >> 10, rem = id & 1023;
        int row = rem >> 3, c = rem & 7;
        unsigned dst = stg + part * 16384 + SWZ(row * 128 + c * 16);
        int wx = row + dx;
        bool ok = rowok && ((unsigned)wx < 128u);
        const __nv_bfloat16* base = part ? g_xlo : g_xhi;
        const __nv_bfloat16* src = base +
            (ok ? ((size_t)(yy * 128 + wx) * CC + ic0 + c * 8) : 0);
        cp16(dst, src, ok ? 16u : 0u);
    }
    #pragma unroll
    for (int j = 0; j < 8; j++){
        int id = tid + j * 256;
        int part = id >> 10, rem = id & 1023;
        int row = rem >> 3, c = rem & 7;
        unsigned dst = stg + 32768 + part * 16384 + SWZ(row * 128 + c * 16);
        const __nv_bfloat16* base = part ? g_wlo : g_whi;
        cp16(dst, base + (size_t)tap * (CC * CC) + (size_t)(oc0 + row) * CC
                 + ic0 + c * 8, 16u);
    }
}

__global__ void __launch_bounds__(256, 1) conv_mma_kernel(const float* __restrict__ bias){
    extern __shared__ __align__(1024) char dsm[];
    const unsigned sb = smem_u32(dsm);
    const int tid = threadIdx.x, lane = tid & 31, wid = tid >> 5;
    const int y = blockIdx.x, oc0 = blockIdx.y * 128;
    const int m0 = (wid & 3) * 32, n0 = (wid >> 2) * 64;

    float acc[2][8][4];
    #pragma unroll
    for (int a = 0; a < 2; a++)
        #pragma unroll
        for (int b = 0; b < 8; b++)
            #pragma unroll
            for (int c = 0; c < 4; c++) acc[a][b][c] = 0.f;

    const int a_row = lane & 15;
    const int a_kad = (lane >> 4) << 4;
    const int b_row = ((lane >> 4) << 3) + (lane & 7);
    const int b_kad = ((lane >> 3) & 1) << 4;

    conv_load_chunk(sb, 0, 0, y, oc0, tid);
    CP_COMMIT();

    for (int i = 0; i < 72; i++){
        const int s = i & 1;
        if (i < 71){
            conv_load_chunk(sb, i + 1, (i + 1) & 1, y, oc0, tid);
            CP_COMMIT();
            CP_WAIT1();
        } else {
            CP_WAIT0();
        }
        __syncthreads();

        const unsigned Ah = sb + s * CSTG;
        const unsigned Al = Ah + 16384;
        const unsigned Bh = Ah + 32768;
        const unsigned Bl = Ah + 49152;

        #pragma unroll
        for (int k16 = 0; k16 < 4; k16++){
            const int koff = k16 * 32;
            unsigned ah[2][4], al[2][4];
            #pragma unroll
            for (int mt = 0; mt < 2; mt++){
                unsigned off = SWZ((m0 + mt * 16 + a_row) * 128 + koff + a_kad);
                ldm4(ah[mt], Ah + off);
                ldm4(al[mt], Al + off);
            }
            unsigned bh[4][4], bl[4][4];
            #pragma unroll
            for (int bt = 0; bt < 4; bt++){
                unsigned off = SWZ((n0 + bt * 16 + b_row) * 128 + koff + b_kad);
                ldm4(bh[bt], Bh + off);
                ldm4(bl[bt], Bl + off);
            }
            #pragma unroll
            for (int mt = 0; mt < 2; mt++)
                #pragma unroll
                for (int bt = 0; bt < 4; bt++){
                    mma16816(acc[mt][2*bt],   ah[mt], &bh[bt][0]);
                    mma16816(acc[mt][2*bt],   ah[mt], &bl[bt][0]);
                    mma16816(acc[mt][2*bt],   al[mt], &bh[bt][0]);
                    mma16816(acc[mt][2*bt+1], ah[mt], &bh[bt][2]);
                    mma16816(acc[mt][2*bt+1], ah[mt], &bl[bt][2]);
                    mma16816(acc[mt][2*bt+1], al[mt], &bh[bt][2]);
                }
        }
        __syncthreads();
    }

    // Epilogue: bias + relu, split to bf16 hi/lo, store NHWC mid
    const int er = lane >> 2;
    const int ec = (lane & 3) * 2;
    #pragma unroll
    for (int mt = 0; mt < 2; mt++){
        #pragma unroll
        for (int nt = 0; nt < 8; nt++){
            const int oc = oc0 + n0 + nt * 8 + ec;
            const float2 b2 = *(const float2*)&bias[oc];
            #pragma unroll
            for (int h = 0; h < 2; h++){
                const int pm = m0 + mt * 16 + er + h * 8;
                const size_t p = (size_t)y * 128 + pm;
                float v0 = fmaxf(acc[mt][nt][2*h+0] + b2.x, 0.f);
                float v1 = fmaxf(acc[mt][nt][2*h+1] + b2.y, 0.f);
                __nv_bfloat16 h0 = __float2bfloat16(v0);
                __nv_bfloat16 h1 = __float2bfloat16(v1);
                __nv_bfloat16 l0 = __float2bfloat16(v0 - __bfloat162float(h0));
                __nv_bfloat16 l1 = __float2bfloat16(v1 - __bfloat162float(h1));
                unsigned hp = (unsigned)*(unsigned short*)&h0
                            | ((unsigned)*(unsigned short*)&h1 << 16);
                unsigned lp = (unsigned)*(unsigned short*)&l0
                            | ((unsigned)*(unsigned short*)&l1 << 16);
                *(unsigned*)&g_mhi[p * CC + oc] = hp;
                *(unsigned*)&g_mlo[p * CC + oc] = lp;
            }
        }
    }
}

// ---------------------------------------------------------------------------
// Head GEMM via mma.sync: M=128/CTA (grid 128), N=72, K=512. B smem-resident.
// ---------------------------------------------------------------------------
#define HB    147456                     // 8 kc x (hi 9216 + lo 9216)
#define HASTG 32768
#define HDYN  (HB + 2*HASTG)             // 212992

__device__ __forceinline__ void head_load_A(unsigned sb, int i, int s,
                                            int p0, int tid){
    const unsigned ast = sb + HB + s * HASTG;
    const int ic0 = i * 64;
    #pragma unroll
    for (int j = 0; j < 8; j++){
        int id = tid + j * 256;
        int part = id >> 10, rem = id & 1023;
        int row = rem >> 3, c = rem & 7;
        unsigned dst = ast + part * 16384 + SWZ(row * 128 + c * 16);
        const __nv_bfloat16* base = part ? g_mlo : g_mhi;
        cp16(dst, base + (size_t)(p0 + row) * CC + ic0 + c * 8, 16u);
    }
}

__global__ void __launch_bounds__(256, 1) head_mma_kernel(
        const float* __restrict__ loc_b, const float* __restrict__ score_b,
        float* __restrict__ out){
    extern __shared__ __align__(1024) char dsm[];
    const unsigned sb = smem_u32(dsm);
    const int tid = threadIdx.x, lane = tid & 31, wid = tid >> 5;
    const int p0 = blockIdx.x * 128;
    const int m0 = wid * 16;

    float acc[9][4];
    #pragma unroll
    for (int n = 0; n < 9; n++)
        #pragma unroll
        for (int c = 0; c < 4; c++) acc[n][c] = 0.f;

    // B preload (147456 B = 9216 cp16 ops)
    #pragma unroll
    for (int j = 0; j < 36; j++){
        int id = tid + j * 256;
        int kc  = id / 1152;
        int rem = id % 1152;
        int part = rem / 576;
        int r2   = rem % 576;
        int row  = r2 >> 3, c = r2 & 7;
        unsigned dst = sb + kc * 18432 + part * 9216 + SWZ(row * 128 + c * 16);
        const __nv_bfloat16* base = part ? g_hwlo : g_hwhi;
        cp16(dst, base + kc * 4608 + row * 64 + c * 8, 16u);
    }
    head_load_A(sb, 0, 0, p0, tid);
    CP_COMMIT();

    const int a_row = lane & 15;
    const int a_kad = (lane >> 4) << 4;
    const int b_row = lane & 7;
    const int b_kad = ((lane >> 3) & 1) << 4;

    for (int i = 0; i < 8; i++){
        const int s = i & 1;
        if (i < 7){
            head_load_A(sb, i + 1, (i + 1) & 1, p0, tid);
            CP_COMMIT();
            CP_WAIT1();
        } else {
            CP_WAIT0();
        }
        __syncthreads();

        const unsigned Ah = sb + HB + s * HASTG;
        const unsigned Al = Ah + 16384;
        const unsigned Bh = sb + i * 18432;
        const unsigned Bl = Bh + 9216;

        #pragma unroll
        for (int k16 = 0; k16 < 4; k16++){
            const int koff = k16 * 32;
            unsigned ah[4], al[4];
            {
                unsigned off = SWZ((m0 + a_row) * 128 + koff + a_kad);
                ldm4(ah, Ah + off);
                ldm4(al, Al + off);
            }
            #pragma unroll
            for (int nt = 0; nt < 9; nt++){
                unsigned off = SWZ((nt * 8 + b_row) * 128 + koff + b_kad);
                unsigned bh2[2], bl2[2];
                ldm2(bh2, Bh + off);
                ldm2(bl2, Bl + off);
                mma16816(acc[nt], ah, bh2);
                mma16816(acc[nt], ah, bl2);
                mma16816(acc[nt], al, bh2);
            }
        }
        __syncthreads();
    }

    // Epilogue: bias, scatter to loc/cls output slots
    const int er = lane >> 2;
    const int ec = (lane & 3) * 2;
    #pragma unroll
    for (int nt = 0; nt < 9; nt++){
        const int col = nt * 8 + ec;
        const int p1 = p0 + m0 + er;
        const int p2 = p1 + 8;
        if (col < 48){
            float2 b2 = *(const float2*)&loc_b[col];
            *(float2*)&out[LOC_OFF + (size_t)p1 * 48 + col] =
                make_float2(acc[nt][0] + b2.x, acc[nt][1] + b2.y);
            *(float2*)&out[LOC_OFF + (size_t)p2 * 48 + col] =
                make_float2(acc[nt][2] + b2.x, acc[nt][3] + b2.y);
        } else {
            const int cc = col - 48;
            float2 b2 = *(const float2*)&score_b[cc];
            *(float2*)&out[CLS_OFF + (size_t)p1 * 24 + cc] =
                make_float2(acc[nt][0] + b2.x, acc[nt][1] + b2.y);
            *(float2*)&out[CLS_OFF + (size_t)p2 * 24 + cc] =
                make_float2(acc[nt][2] + b2.x, acc[nt][3] + b2.y);
        }
    }
}

// ---------------------------------------------------------------------------
// roi decode (anchor quirk: xi = p>>7, yi = p&127 — x varies slowly)
// ---------------------------------------------------------------------------
__global__ void roi_kernel(float* __restrict__ out){
    int i = blockIdx.x * 256 + threadIdx.x;
    if (i >= HWSZ * NANCH) return;
    int p = i / NANCH, a = i % NANCH;
    float gx = (float)((p >> 7) * 16);
    float gy = (float)((p & 127) * 16);
    const float RAT[3] = {0.5f, 1.0f, 2.0f};
    const float SIZ[4] = {64.f, 128.f, 256.f, 512.f};
    float r = RAT[a >> 2], s = SIZ[a & 3];
    float hr = sqrtf(r);
    float aw = rintf(0.5f * ((1.0f / hr) * s));
    float ah = rintf(0.5f * (hr * s));
    float4 l = *(const float4*)&out[LOC_OFF + (size_t)i * 4];
    float4 ro;
    ro.x = l.x * aw + gx;
    ro.y = l.y * ah + gy;
    ro.z = expf(l.z) * aw;
    ro.w = expf(l.w) * ah;
    *(float4*)&out[ROI_OFF + (size_t)i * 4] = ro;
}

// ---------------------------------------------------------------------------
extern "C" void kernel_launch(void* const* d_in, const int* in_sizes, int n_in,
                              void* d_out, int out_size){
    const float* x       = (const float*)d_in[0];
    const float* conv1_w = (const float*)d_in[1];
    const float* conv1_b = (const float*)d_in[2];
    const float* score_w = (const float*)d_in[3];
    const float* score_b = (const float*)d_in[4];
    const float* loc_w   = (const float*)d_in[5];
    const float* loc_b   = (const float*)d_in[6];
    float* out = (float*)d_out;

    cudaFuncSetAttribute(conv_mma_kernel,
        cudaFuncAttributeMaxDynamicSharedMemorySize, CDYN);
    cudaFuncSetAttribute(head_mma_kernel,
        cudaFuncAttributeMaxDynamicSharedMemorySize, HDYN);

    prep_x_kernel<<<dim3(HWSZ / 32, CC / 32), dim3(32, 8)>>>(x);
    prep_w_kernel<<<(9 * CC * CC + 255) / 256, 256>>>(conv1_w);
    prep_hw_kernel<<<(8 * 72 * 64 + 255) / 256, 256>>>(loc_w, score_w);

    conv_mma_kernel<<<dim3(128, 4), 256, CDYN>>>(conv1_b);

    head_mma_kernel<<<128, 256, HDYN>>>(loc_b, score_b, out);

    roi_kernel<<<(HWSZ * NANCH + 255) / 256, 256>>>(out);
}

// round 4
// speedup vs baseline: 6.0935x; 1.4357x over previous
#include <cuda_runtime.h>
#include <cuda_fp16.h>

#define HH 128
#define WW 128
#define CC 512
#define HWSZ (HH*WW)
#define NANCH 12

#define LOC_OFF   0
#define CLS_OFF   786432
#define ROI_OFF   1179648

// ---------------------------------------------------------------------------
// Global scratch (allocation-free)
// ---------------------------------------------------------------------------
__device__ __align__(256) __half g_xhi[HWSZ * CC];      // x NHWC hi
__device__ __align__(256) __half g_xlo[HWSZ * CC];      // x NHWC lo
__device__ __align__(256) __half g_wh [9 * CC * CC];    // conv W [tap][oc][ic] fp16
__device__ __align__(256) __half g_mhi[HWSZ * CC];      // mid NHWC hi
__device__ __align__(256) __half g_mlo[HWSZ * CC];      // mid NHWC lo
__device__ __align__(256) __half g_hw [8 * 72 * 64];    // head W [kc][row72][64] fp16

// ---------------------------------------------------------------------------
// Helpers (plain sm_80+ PTX, legal on the non-'a' compute_103 target)
// ---------------------------------------------------------------------------
__device__ __forceinline__ unsigned smem_u32(const void* p){
    unsigned a;
    asm("{ .reg .u64 t; cvta.to.shared.u64 t, %1; cvt.u32.u64 %0, t; }" : "=r"(a) : "l"(p));
    return a;
}
#define SWZ(b) ((unsigned)(b) ^ ((((unsigned)(b)) >> 3) & 0x70u))

__device__ __forceinline__ void cp16(unsigned dst, const void* src, unsigned sz){
    asm volatile("cp.async.cg.shared.global [%0], [%1], 16, %2;"
        :: "r"(dst), "l"(src), "r"(sz) : "memory");
}
#define CP_COMMIT() asm volatile("cp.async.commit_group;" ::: "memory")
#define CP_WAIT(n)  asm volatile("cp.async.wait_group %0;" :: "n"(n) : "memory")

__device__ __forceinline__ void ldm4(unsigned* r, unsigned addr){
    asm volatile("ldmatrix.sync.aligned.m8n8.x4.shared.b16 {%0,%1,%2,%3}, [%4];"
        : "=r"(r[0]), "=r"(r[1]), "=r"(r[2]), "=r"(r[3]) : "r"(addr));
}
__device__ __forceinline__ void ldm2(unsigned* r, unsigned addr){
    asm volatile("ldmatrix.sync.aligned.m8n8.x2.shared.b16 {%0,%1}, [%2];"
        : "=r"(r[0]), "=r"(r[1]) : "r"(addr));
}
__device__ __forceinline__ void mma16816(float* d, const unsigned* a, const unsigned* b){
    asm volatile("mma.sync.aligned.m16n8k16.row.col.f32.f16.f16.f32 "
        "{%0,%1,%2,%3}, {%4,%5,%6,%7}, {%8,%9}, {%0,%1,%2,%3};"
        : "+f"(d[0]), "+f"(d[1]), "+f"(d[2]), "+f"(d[3])
        : "r"(a[0]), "r"(a[1]), "r"(a[2]), "r"(a[3]), "r"(b[0]), "r"(b[1]));
}

// ---------------------------------------------------------------------------
// Prep kernels
// ---------------------------------------------------------------------------
__global__ void prep_x_kernel(const float* __restrict__ x){
    __shared__ float tile[32][33];
    int hw0 = blockIdx.x * 32, c0 = blockIdx.y * 32;
    int tx = threadIdx.x, ty = threadIdx.y;
    #pragma unroll
    for (int i = 0; i < 32; i += 8)
        tile[ty + i][tx] = x[(size_t)(c0 + ty + i) * HWSZ + hw0 + tx];
    __syncthreads();
    #pragma unroll
    for (int i = 0; i < 32; i += 8){
        int hw = ty + i;
        float v = tile[tx][hw];
        __half hi = __float2half(v);
        size_t o = (size_t)(hw0 + hw) * CC + c0 + tx;
        g_xhi[o] = hi;
        g_xlo[o] = __float2half(v - __half2float(hi));
    }
}

__global__ void prep_w_kernel(const float* __restrict__ w){
    int idx = blockIdx.x * 256 + threadIdx.x;
    if (idx >= 9 * CC * CC) return;
    int tap = idx / (CC * CC);
    int rem = idx % (CC * CC);
    int oc  = rem >> 9;
    int ic  = rem & 511;
    g_wh[idx] = __float2half(w[(size_t)oc * (CC * 9) + ic * 9 + tap]);
}

__global__ void prep_hw_kernel(const float* __restrict__ loc_w,
                               const float* __restrict__ score_w){
    int idx = blockIdx.x * 256 + threadIdx.x;
    if (idx >= 8 * 72 * 64) return;
    int kc  = idx / (72 * 64);
    int rem = idx % (72 * 64);
    int row = rem >> 6;
    int k   = rem & 63;
    float v = (row < 48) ? loc_w[row * CC + kc * 64 + k]
                         : score_w[(row - 48) * CC + kc * 64 + k];
    g_hw[idx] = __float2half(v);
}

// ---------------------------------------------------------------------------
// Conv 3x3: 2-pass fp16 (a = x hi/lo, b = w single). grid(128, 4), 512 thr.
// CTA tile M=128 x N=128; K = 9 taps x 512 ic in 72 chunks of 64.
// Stage = Ah16K + Al16K + B16K = 48KB; 4-deep cp.async pipeline (192KB).
// 16 warps, warp tile 32x32.
// ---------------------------------------------------------------------------
#define CSTG  49152
#define CDYN  (4*CSTG)

__device__ __forceinline__ void conv_load_chunk(unsigned sb, int i, int s,
                                                int y, int oc0, int tid){
    const int tap = i >> 3;
    const int ic0 = (i & 7) << 6;
    const int dy = tap / 3 - 1, dx = tap % 3 - 1;
    const int yy = y + dy;
    const bool rowok = ((unsigned)yy < 128u);
    const unsigned stg = sb + s * CSTG;
    #pragma unroll
    for (int j = 0; j < 6; j++){
        int id = tid + j * 512;
        if (id < 2048){                       // A hi/lo
            int part = id >> 10, rem = id & 1023;
            int row = rem >> 3, c = rem & 7;
            unsigned dst = stg + part * 16384 + SWZ(row * 128 + c * 16);
            int wx = row + dx;
            bool ok = rowok && ((unsigned)wx < 128u);
            const __half* base = part ? g_xlo : g_xhi;
            const __half* src = base +
                (ok ? ((size_t)(yy * 128 + wx) * CC + ic0 + c * 8) : 0);
            cp16(dst, src, ok ? 16u : 0u);
        } else {                              // B single
            int idb = id - 2048;              // 0..1023
            int row = idb >> 3, c = idb & 7;
            unsigned dst = stg + 32768 + SWZ(row * 128 + c * 16);
            cp16(dst, g_wh + (size_t)tap * (CC * CC)
                     + (size_t)(oc0 + row) * CC + ic0 + c * 8, 16u);
        }
    }
}

__global__ void __launch_bounds__(512, 1) conv_mma_kernel(const float* __restrict__ bias){
    extern __shared__ __align__(1024) char dsm[];
    const unsigned sb = smem_u32(dsm);
    const int tid = threadIdx.x, lane = tid & 31, wid = tid >> 5;
    const int y = blockIdx.x, oc0 = blockIdx.y * 128;
    const int m0 = (wid & 3) * 32, n0 = (wid >> 2) * 32;

    float acc[2][4][4];
    #pragma unroll
    for (int a = 0; a < 2; a++)
        #pragma unroll
        for (int b = 0; b < 4; b++)
            #pragma unroll
            for (int c = 0; c < 4; c++) acc[a][b][c] = 0.f;

    const int a_row = lane & 15;
    const int a_kad = (lane >> 4) << 4;
    const int b_row = ((lane >> 4) << 3) + (lane & 7);
    const int b_kad = ((lane >> 3) & 1) << 4;

    conv_load_chunk(sb, 0, 0, y, oc0, tid); CP_COMMIT();
    conv_load_chunk(sb, 1, 1, y, oc0, tid); CP_COMMIT();

    for (int i = 0; i < 72; i++){
        const int s = i & 3;
        if (i + 2 < 72){
            conv_load_chunk(sb, i + 2, (i + 2) & 3, y, oc0, tid);
            CP_COMMIT();
            CP_WAIT(2);
        } else if (i + 1 < 72){
            CP_WAIT(1);
        } else {
            CP_WAIT(0);
        }
        __syncthreads();

        const unsigned Ah = sb + s * CSTG;
        const unsigned Al = Ah + 16384;
        const unsigned Bh = Ah + 32768;

        #pragma unroll
        for (int k16 = 0; k16 < 4; k16++){
            const int koff = k16 * 32;
            unsigned ah[2][4], al[2][4];
            #pragma unroll
            for (int mt = 0; mt < 2; mt++){
                unsigned off = SWZ((m0 + mt * 16 + a_row) * 128 + koff + a_kad);
                ldm4(ah[mt], Ah + off);
                ldm4(al[mt], Al + off);
            }
            unsigned bh[2][4];
            #pragma unroll
            for (int bt = 0; bt < 2; bt++){
                unsigned off = SWZ((n0 + bt * 16 + b_row) * 128 + koff + b_kad);
                ldm4(bh[bt], Bh + off);
            }
            #pragma unroll
            for (int mt = 0; mt < 2; mt++)
                #pragma unroll
                for (int bt = 0; bt < 2; bt++){
                    mma16816(acc[mt][2*bt],   ah[mt], &bh[bt][0]);
                    mma16816(acc[mt][2*bt],   al[mt], &bh[bt][0]);
                    mma16816(acc[mt][2*bt+1], ah[mt], &bh[bt][2]);
                    mma16816(acc[mt][2*bt+1], al[mt], &bh[bt][2]);
                }
        }
    }

    // Epilogue: bias + relu, split to fp16 hi/lo, store NHWC mid
    const int er = lane >> 2;
    const int ec = (lane & 3) * 2;
    #pragma unroll
    for (int mt = 0; mt < 2; mt++){
        #pragma unroll
        for (int nt = 0; nt < 4; nt++){
            const int oc = oc0 + n0 + nt * 8 + ec;
            const float2 b2 = *(const float2*)&bias[oc];
            #pragma unroll
            for (int h = 0; h < 2; h++){
                const size_t p = (size_t)y * 128 + m0 + mt * 16 + er + h * 8;
                float v0 = fmaxf(acc[mt][nt][2*h+0] + b2.x, 0.f);
                float v1 = fmaxf(acc[mt][nt][2*h+1] + b2.y, 0.f);
                __half h0 = __float2half(v0);
                __half h1 = __float2half(v1);
                __half l0 = __float2half(v0 - __half2float(h0));
                __half l1 = __float2half(v1 - __half2float(h1));
                unsigned hp = (unsigned)*(unsigned short*)&h0
                            | ((unsigned)*(unsigned short*)&h1 << 16);
                unsigned lp = (unsigned)*(unsigned short*)&l0
                            | ((unsigned)*(unsigned short*)&l1 << 16);
                *(unsigned*)&g_mhi[p * CC + oc] = hp;
                *(unsigned*)&g_mlo[p * CC + oc] = lp;
            }
        }
    }
}

// ---------------------------------------------------------------------------
// Head GEMM: M=128/CTA (grid 128), N=72, K=512. 2-pass fp16, B smem-resident.
// ---------------------------------------------------------------------------
#define HB    73728                      // 8 kc x 9216 (single fp16)
#define HASTG 32768                      // Ah 16K + Al 16K
#define HDYN  (HB + 2*HASTG)             // 139264

__device__ __forceinline__ void head_load_A(unsigned sb, int i, int s,
                                            int p0, int tid){
    const unsigned ast = sb + HB + s * HASTG;
    const int ic0 = i * 64;
    #pragma unroll
    for (int j = 0; j < 8; j++){
        int id = tid + j * 256;
        int part = id >> 10, rem = id & 1023;
        int row = rem >> 3, c = rem & 7;
        unsigned dst = ast + part * 16384 + SWZ(row * 128 + c * 16);
        const __half* base = part ? g_mlo : g_mhi;
        cp16(dst, base + (size_t)(p0 + row) * CC + ic0 + c * 8, 16u);
    }
}

__global__ void __launch_bounds__(256, 1) head_mma_kernel(
        const float* __restrict__ loc_b, const float* __restrict__ score_b,
        float* __restrict__ out){
    extern __shared__ __align__(1024) char dsm[];
    const unsigned sb = smem_u32(dsm);
    const int tid = threadIdx.x, lane = tid & 31, wid = tid >> 5;
    const int p0 = blockIdx.x * 128;
    const int m0 = wid * 16;

    float acc[9][4];
    #pragma unroll
    for (int n = 0; n < 9; n++)
        #pragma unroll
        for (int c = 0; c < 4; c++) acc[n][c] = 0.f;

    // B preload: 73728 B = 4608 cp16
    #pragma unroll
    for (int j = 0; j < 18; j++){
        int id = tid + j * 256;
        int kc  = id / 576;
        int rem = id % 576;
        int row = rem >> 3, c = rem & 7;
        unsigned dst = sb + kc * 9216 + SWZ(row * 128 + c * 16);
        cp16(dst, g_hw + kc * 4608 + row * 64 + c * 8, 16u);
    }
    head_load_A(sb, 0, 0, p0, tid);
    CP_COMMIT();

    const int a_row = lane & 15;
    const int a_kad = (lane >> 4) << 4;
    const int b_row = lane & 7;
    const int b_kad = ((lane >> 3) & 1) << 4;

    for (int i = 0; i < 8; i++){
        const int s = i & 1;
        if (i < 7){
            head_load_A(sb, i + 1, (i + 1) & 1, p0, tid);
            CP_COMMIT();
            CP_WAIT(1);
        } else {
            CP_WAIT(0);
        }
        __syncthreads();

        const unsigned Ah = sb + HB + s * HASTG;
        const unsigned Al = Ah + 16384;
        const unsigned Bh = sb + i * 9216;

        #pragma unroll
        for (int k16 = 0; k16 < 4; k16++){
            const int koff = k16 * 32;
            unsigned ah[4], al[4];
            {
                unsigned off = SWZ((m0 + a_row) * 128 + koff + a_kad);
                ldm4(ah, Ah + off);
                ldm4(al, Al + off);
            }
            #pragma unroll
            for (int nt = 0; nt < 9; nt++){
                unsigned off = SWZ((nt * 8 + b_row) * 128 + koff + b_kad);
                unsigned bh2[2];
                ldm2(bh2, Bh + off);
                mma16816(acc[nt], ah, bh2);
                mma16816(acc[nt], al, bh2);
            }
        }
        __syncthreads();
    }

    // Epilogue: bias, scatter to loc/cls output slots
    const int er = lane >> 2;
    const int ec = (lane & 3) * 2;
    #pragma unroll
    for (int nt = 0; nt < 9; nt++){
        const int col = nt * 8 + ec;
        const int p1 = p0 + m0 + er;
        const int p2 = p1 + 8;
        if (col < 48){
            float2 b2 = *(const float2*)&loc_b[col];
            *(float2*)&out[LOC_OFF + (size_t)p1 * 48 + col] =
                make_float2(acc[nt][0] + b2.x, acc[nt][1] + b2.y);
            *(float2*)&out[LOC_OFF + (size_t)p2 * 48 + col] =
                make_float2(acc[nt][2] + b2.x, acc[nt][3] + b2.y);
        } else {
            const int cc2 = col - 48;
            float2 b2 = *(const float2*)&score_b[cc2];
            *(float2*)&out[CLS_OFF + (size_t)p1 * 24 + cc2] =
                make_float2(acc[nt][0] + b2.x, acc[nt][1] + b2.y);
            *(float2*)&out[CLS_OFF + (size_t)p2 * 24 + cc2] =
                make_float2(acc[nt][2] + b2.x, acc[nt][3] + b2.y);
        }
    }
}

// ---------------------------------------------------------------------------
// roi decode (anchor quirk: xi = p>>7, yi = p&127 — x varies slowly)
// ---------------------------------------------------------------------------
__global__ void roi_kernel(float* __restrict__ out){
    int i = blockIdx.x * 256 + threadIdx.x;
    if (i >= HWSZ * NANCH) return;
    int p = i / NANCH, a = i % NANCH;
    float gx = (float)((p >> 7) * 16);
    float gy = (float)((p & 127) * 16);
    const float RAT[3] = {0.5f, 1.0f, 2.0f};
    const float SIZ[4] = {64.f, 128.f, 256.f, 512.f};
    float r = RAT[a >> 2], s = SIZ[a & 3];
    float hr = sqrtf(r);
    float aw = rintf(0.5f * ((1.0f / hr) * s));
    float ah = rintf(0.5f * (hr * s));
    float4 l = *(const float4*)&out[LOC_OFF + (size_t)i * 4];
    float4 ro;
    ro.x = l.x * aw + gx;
    ro.y = l.y * ah + gy;
    ro.z = expf(l.z) * aw;
    ro.w = expf(l.w) * ah;
    *(float4*)&out[ROI_OFF + (size_t)i * 4] = ro;
}

// ---------------------------------------------------------------------------
extern "C" void kernel_launch(void* const* d_in, const int* in_sizes, int n_in,
                              void* d_out, int out_size){
    const float* x       = (const float*)d_in[0];
    const float* conv1_w = (const float*)d_in[1];
    const float* conv1_b = (const float*)d_in[2];
    const float* score_w = (const float*)d_in[3];
    const float* score_b = (const float*)d_in[4];
    const float* loc_w   = (const float*)d_in[5];
    const float* loc_b   = (const float*)d_in[6];
    float* out = (float*)d_out;

    cudaFuncSetAttribute(conv_mma_kernel,
        cudaFuncAttributeMaxDynamicSharedMemorySize, CDYN);
    cudaFuncSetAttribute(head_mma_kernel,
        cudaFuncAttributeMaxDynamicSharedMemorySize, HDYN);

    prep_x_kernel<<<dim3(HWSZ / 32, CC / 32), dim3(32, 8)>>>(x);
    prep_w_kernel<<<(9 * CC * CC + 255) / 256, 256>>>(conv1_w);
    prep_hw_kernel<<<(8 * 72 * 64 + 255) / 256, 256>>>(loc_w, score_w);

    conv_mma_kernel<<<dim3(128, 4), 512, CDYN>>>(conv1_b);

    head_mma_kernel<<<128, 256, HDYN>>>(loc_b, score_b, out);

    roi_kernel<<<(HWSZ * NANCH + 255) / 256, 256>>>(out);
}

// round 5
// speedup vs baseline: 6.9754x; 1.1447x over previous
#include <cuda_runtime.h>
#include <cuda_fp16.h>

#define HH 128
#define WW 128
#define CC 512
#define HWSZ (HH*WW)
#define NANCH 12

#define LOC_OFF   0
#define CLS_OFF   786432
#define ROI_OFF   1179648

// ---------------------------------------------------------------------------
// Global scratch (allocation-free)
// ---------------------------------------------------------------------------
__device__ __align__(256) __half g_xhi[HWSZ * CC];        // x NHWC hi
__device__ __align__(256) __half g_xlo[HWSZ * CC];        // x NHWC lo
__device__ __align__(256) __half g_wh [9 * CC * CC];      // conv W [tap][oc][ic]
__device__ __align__(256) float  g_part[4][HWSZ * CC];    // K-split partials (134MB)
__device__ __align__(256) __half g_mhi[HWSZ * CC];        // mid NHWC hi
__device__ __align__(256) __half g_mlo[HWSZ * CC];        // mid NHWC lo
__device__ __align__(256) __half g_hw [8 * 72 * 64];      // head W [kc][row72][64]

// ---------------------------------------------------------------------------
// Helpers (plain sm_80+ PTX, legal on the non-'a' compute_103 target)
// ---------------------------------------------------------------------------
__device__ __forceinline__ unsigned smem_u32(const void* p){
    unsigned a;
    asm("{ .reg .u64 t; cvta.to.shared.u64 t, %1; cvt.u32.u64 %0, t; }" : "=r"(a) : "l"(p));
    return a;
}
#define SWZ(b) ((unsigned)(b) ^ ((((unsigned)(b)) >> 3) & 0x70u))

__device__ __forceinline__ void cp16(unsigned dst, const void* src, unsigned sz){
    asm volatile("cp.async.cg.shared.global [%0], [%1], 16, %2;"
        :: "r"(dst), "l"(src), "r"(sz) : "memory");
}
#define CP_COMMIT() asm volatile("cp.async.commit_group;" ::: "memory")
#define CP_WAIT(n)  asm volatile("cp.async.wait_group %0;" :: "n"(n) : "memory")

__device__ __forceinline__ void ldm4(unsigned* r, unsigned addr){
    asm volatile("ldmatrix.sync.aligned.m8n8.x4.shared.b16 {%0,%1,%2,%3}, [%4];"
        : "=r"(r[0]), "=r"(r[1]), "=r"(r[2]), "=r"(r[3]) : "r"(addr));
}
__device__ __forceinline__ void ldm2(unsigned* r, unsigned addr){
    asm volatile("ldmatrix.sync.aligned.m8n8.x2.shared.b16 {%0,%1}, [%2];"
        : "=r"(r[0]), "=r"(r[1]) : "r"(addr));
}
__device__ __forceinline__ void mma16816(float* d, const unsigned* a, const unsigned* b){
    asm volatile("mma.sync.aligned.m16n8k16.row.col.f32.f16.f16.f32 "
        "{%0,%1,%2,%3}, {%4,%5,%6,%7}, {%8,%9}, {%0,%1,%2,%3};"
        : "+f"(d[0]), "+f"(d[1]), "+f"(d[2]), "+f"(d[3])
        : "r"(a[0]), "r"(a[1]), "r"(a[2]), "r"(a[3]), "r"(b[0]), "r"(b[1]));
}

// ---------------------------------------------------------------------------
// Prep kernels
// ---------------------------------------------------------------------------
__global__ void prep_x_kernel(const float* __restrict__ x){
    __shared__ float tile[32][33];
    int hw0 = blockIdx.x * 32, c0 = blockIdx.y * 32;
    int tx = threadIdx.x, ty = threadIdx.y;
    #pragma unroll
    for (int i = 0; i < 32; i += 8)
        tile[ty + i][tx] = x[(size_t)(c0 + ty + i) * HWSZ + hw0 + tx];
    __syncthreads();
    #pragma unroll
    for (int i = 0; i < 32; i += 8){
        int hw = ty + i;
        float v = tile[tx][hw];
        __half hi = __float2half(v);
        size_t o = (size_t)(hw0 + hw) * CC + c0 + tx;
        g_xhi[o] = hi;
        g_xlo[o] = __float2half(v - __half2float(hi));
    }
}

__global__ void prep_w_kernel(const float* __restrict__ w){
    int idx = blockIdx.x * 256 + threadIdx.x;
    if (idx >= 9 * CC * CC) return;
    int tap = idx / (CC * CC);
    int rem = idx % (CC * CC);
    int oc  = rem >> 9;
    int ic  = rem & 511;
    g_wh[idx] = __float2half(w[(size_t)oc * (CC * 9) + ic * 9 + tap]);
}

__global__ void prep_hw_kernel(const float* __restrict__ loc_w,
                               const float* __restrict__ score_w){
    int idx = blockIdx.x * 256 + threadIdx.x;
    if (idx >= 8 * 72 * 64) return;
    int kc  = idx / (72 * 64);
    int rem = idx % (72 * 64);
    int row = rem >> 6;
    int k   = rem & 63;
    float v = (row < 48) ? loc_w[row * CC + kc * 64 + k]
                         : score_w[(row - 48) * CC + kc * 64 + k];
    g_hw[idx] = __float2half(v);
}

// ---------------------------------------------------------------------------
// Conv 3x3, K-split x4. grid (y=128, ocg=4, ks=4) = 2048 CTAs, 256 threads.
// CTA: M=128 pos x N=128 oc x K=18 chunks of 64 ic. Warp tile 32x64 (8 warps).
// Stage = Ah16K + Al16K + B16K = 48KB, 2 stages = 96KB -> 2 CTAs/SM.
// Writes raw fp32 partials to g_part[ks].
// ---------------------------------------------------------------------------
#define CSTG  49152
#define CDYN  (2*CSTG)

__device__ __forceinline__ void conv_load_chunk(unsigned sb, int ci, int s,
                                                int y, int oc0, int tid){
    const int tap = ci >> 3;
    const int ic0 = (ci & 7) << 6;
    const int dy = tap / 3 - 1, dx = tap % 3 - 1;
    const int yy = y + dy;
    const bool rowok = ((unsigned)yy < 128u);
    const unsigned stg = sb + s * CSTG;
    #pragma unroll
    for (int j = 0; j < 12; j++){
        int id = tid + j * 256;
        if (id < 2048){                       // A hi/lo (2 x 16KB)
            int part = id >> 10, rem = id & 1023;
            int row = rem >> 3, c = rem & 7;
            unsigned dst = stg + part * 16384 + SWZ(row * 128 + c * 16);
            int wx = row + dx;
            bool ok = rowok && ((unsigned)wx < 128u);
            const __half* base = part ? g_xlo : g_xhi;
            const __half* src = base +
                (ok ? ((size_t)(yy * 128 + wx) * CC + ic0 + c * 8) : 0);
            cp16(dst, src, ok ? 16u : 0u);
        } else {                              // B (16KB)
            int idb = id - 2048;
            int row = idb >> 3, c = idb & 7;
            unsigned dst = stg + 32768 + SWZ(row * 128 + c * 16);
            cp16(dst, g_wh + (size_t)tap * (CC * CC)
                     + (size_t)(oc0 + row) * CC + ic0 + c * 8, 16u);
        }
    }
}

__global__ void __launch_bounds__(256, 2) conv_mma_kernel(){
    extern __shared__ __align__(1024) char dsm[];
    const unsigned sb = smem_u32(dsm);
    const int tid = threadIdx.x, lane = tid & 31, wid = tid >> 5;
    const int y = blockIdx.x, oc0 = blockIdx.y * 128, ks = blockIdx.z;
    const int cbase = ks * 18;
    const int m0 = (wid & 3) * 32, n0 = (wid >> 2) * 64;

    float acc[2][8][4];
    #pragma unroll
    for (int a = 0; a < 2; a++)
        #pragma unroll
        for (int b = 0; b < 8; b++)
            #pragma unroll
            for (int c = 0; c < 4; c++) acc[a][b][c] = 0.f;

    const int a_row = lane & 15;
    const int a_kad = (lane >> 4) << 4;
    const int b_row = ((lane >> 4) << 3) + (lane & 7);
    const int b_kad = ((lane >> 3) & 1) << 4;

    conv_load_chunk(sb, cbase, 0, y, oc0, tid);
    CP_COMMIT();

    for (int i = 0; i < 18; i++){
        const int s = i & 1;
        if (i < 17){
            conv_load_chunk(sb, cbase + i + 1, (i + 1) & 1, y, oc0, tid);
            CP_COMMIT();
            CP_WAIT(1);
        } else {
            CP_WAIT(0);
        }
        __syncthreads();

        const unsigned Ah = sb + s * CSTG;
        const unsigned Al = Ah + 16384;
        const unsigned Bh = Ah + 32768;

        #pragma unroll
        for (int k16 = 0; k16 < 4; k16++){
            const int koff = k16 * 32;
            unsigned ah[2][4], al[2][4];
            #pragma unroll
            for (int mt = 0; mt < 2; mt++){
                unsigned off = SWZ((m0 + mt * 16 + a_row) * 128 + koff + a_kad);
                ldm4(ah[mt], Ah + off);
                ldm4(al[mt], Al + off);
            }
            unsigned bh[4][4];
            #pragma unroll
            for (int bt = 0; bt < 4; bt++){
                unsigned off = SWZ((n0 + bt * 16 + b_row) * 128 + koff + b_kad);
                ldm4(bh[bt], Bh + off);
            }
            #pragma unroll
            for (int mt = 0; mt < 2; mt++)
                #pragma unroll
                for (int bt = 0; bt < 4; bt++){
                    mma16816(acc[mt][2*bt],   ah[mt], &bh[bt][0]);
                    mma16816(acc[mt][2*bt],   al[mt], &bh[bt][0]);
                    mma16816(acc[mt][2*bt+1], ah[mt], &bh[bt][2]);
                    mma16816(acc[mt][2*bt+1], al[mt], &bh[bt][2]);
                }
        }
        __syncthreads();   // stage-reuse guard (2-deep pipeline)
    }

    // Store raw fp32 partials
    float* pb = g_part[ks];
    const int er = lane >> 2;
    const int ec = (lane & 3) * 2;
    #pragma unroll
    for (int mt = 0; mt < 2; mt++){
        #pragma unroll
        for (int nt = 0; nt < 8; nt++){
            const int oc = oc0 + n0 + nt * 8 + ec;
            #pragma unroll
            for (int h = 0; h < 2; h++){
                const size_t p = (size_t)y * 128 + m0 + mt * 16 + er + h * 8;
                *(float2*)&pb[p * CC + oc] =
                    make_float2(acc[mt][nt][2*h+0], acc[mt][nt][2*h+1]);
            }
        }
    }
}

// ---------------------------------------------------------------------------
// Epilogue: sum 4 partials + bias + relu, split fp16 hi/lo -> g_mhi/g_mlo
// ---------------------------------------------------------------------------
__global__ void __launch_bounds__(256) mid_epilogue_kernel(const float* __restrict__ bias){
    const size_t i4 = ((size_t)blockIdx.x * 256 + threadIdx.x) * 4;   // 4 oc per thread
    const int oc = (int)(i4 & 511);
    float4 s0 = *(const float4*)&g_part[0][i4];
    float4 s1 = *(const float4*)&g_part[1][i4];
    float4 s2 = *(const float4*)&g_part[2][i4];
    float4 s3 = *(const float4*)&g_part[3][i4];
    float4 b4 = *(const float4*)&bias[oc];
    float v0 = fmaxf(s0.x + s1.x + s2.x + s3.x + b4.x, 0.f);
    float v1 = fmaxf(s0.y + s1.y + s2.y + s3.y + b4.y, 0.f);
    float v2 = fmaxf(s0.z + s1.z + s2.z + s3.z + b4.z, 0.f);
    float v3 = fmaxf(s0.w + s1.w + s2.w + s3.w + b4.w, 0.f);
    __half h0 = __float2half(v0), h1 = __float2half(v1);
    __half h2 = __float2half(v2), h3 = __float2half(v3);
    __half l0 = __float2half(v0 - __half2float(h0));
    __half l1 = __float2half(v1 - __half2float(h1));
    __half l2 = __float2half(v2 - __half2float(h2));
    __half l3 = __float2half(v3 - __half2float(h3));
    uint2 hp = make_uint2((unsigned)*(unsigned short*)&h0 | ((unsigned)*(unsigned short*)&h1 << 16),
                          (unsigned)*(unsigned short*)&h2 | ((unsigned)*(unsigned short*)&h3 << 16));
    uint2 lp = make_uint2((unsigned)*(unsigned short*)&l0 | ((unsigned)*(unsigned short*)&l1 << 16),
                          (unsigned)*(unsigned short*)&l2 | ((unsigned)*(unsigned short*)&l3 << 16));
    *(uint2*)&g_mhi[i4] = hp;
    *(uint2*)&g_mlo[i4] = lp;
}

// ---------------------------------------------------------------------------
// Head GEMM: M=128/CTA (grid 128), N=72, K=512. 2-pass fp16, B smem-resident.
// ---------------------------------------------------------------------------
#define HB    73728
#define HASTG 32768
#define HDYN  (HB + 2*HASTG)

__device__ __forceinline__ void head_load_A(unsigned sb, int i, int s,
                                            int p0, int tid){
    const unsigned ast = sb + HB + s * HASTG;
    const int ic0 = i * 64;
    #pragma unroll
    for (int j = 0; j < 8; j++){
        int id = tid + j * 256;
        int part = id >> 10, rem = id & 1023;
        int row = rem >> 3, c = rem & 7;
        unsigned dst = ast + part * 16384 + SWZ(row * 128 + c * 16);
        const __half* base = part ? g_mlo : g_mhi;
        cp16(dst, base + (size_t)(p0 + row) * CC + ic0 + c * 8, 16u);
    }
}

__global__ void __launch_bounds__(256, 1) head_mma_kernel(
        const float* __restrict__ loc_b, const float* __restrict__ score_b,
        float* __restrict__ out){
    extern __shared__ __align__(1024) char dsm[];
    const unsigned sb = smem_u32(dsm);
    const int tid = threadIdx.x, lane = tid & 31, wid = tid >> 5;
    const int p0 = blockIdx.x * 128;
    const int m0 = wid * 16;

    float acc[9][4];
    #pragma unroll
    for (int n = 0; n < 9; n++)
        #pragma unroll
        for (int c = 0; c < 4; c++) acc[n][c] = 0.f;

    #pragma unroll
    for (int j = 0; j < 18; j++){
        int id = tid + j * 256;
        int kc  = id / 576;
        int rem = id % 576;
        int row = rem >> 3, c = rem & 7;
        unsigned dst = sb + kc * 9216 + SWZ(row * 128 + c * 16);
        cp16(dst, g_hw + kc * 4608 + row * 64 + c * 8, 16u);
    }
    head_load_A(sb, 0, 0, p0, tid);
    CP_COMMIT();

    const int a_row = lane & 15;
    const int a_kad = (lane >> 4) << 4;
    const int b_row = lane & 7;
    const int b_kad = ((lane >> 3) & 1) << 4;

    for (int i = 0; i < 8; i++){
        const int s = i & 1;
        if (i < 7){
            head_load_A(sb, i + 1, (i + 1) & 1, p0, tid);
            CP_COMMIT();
            CP_WAIT(1);
        } else {
            CP_WAIT(0);
        }
        __syncthreads();

        const unsigned Ah = sb + HB + s * HASTG;
        const unsigned Al = Ah + 16384;
        const unsigned Bh = sb + i * 9216;

        #pragma unroll
        for (int k16 = 0; k16 < 4; k16++){
            const int koff = k16 * 32;
            unsigned ah[4], al[4];
            {
                unsigned off = SWZ((m0 + a_row) * 128 + koff + a_kad);
                ldm4(ah, Ah + off);
                ldm4(al, Al + off);
            }
            #pragma unroll
            for (int nt = 0; nt < 9; nt++){
                unsigned off = SWZ((nt * 8 + b_row) * 128 + koff + b_kad);
                unsigned bh2[2];
                ldm2(bh2, Bh + off);
                mma16816(acc[nt], ah, bh2);
                mma16816(acc[nt], al, bh2);
            }
        }
        __syncthreads();
    }

    const int er = lane >> 2;
    const int ec = (lane & 3) * 2;
    #pragma unroll
    for (int nt = 0; nt < 9; nt++){
        const int col = nt * 8 + ec;
        const int p1 = p0 + m0 + er;
        const int p2 = p1 + 8;
        if (col < 48){
            float2 b2 = *(const float2*)&loc_b[col];
            *(float2*)&out[LOC_OFF + (size_t)p1 * 48 + col] =
                make_float2(acc[nt][0] + b2.x, acc[nt][1] + b2.y);
            *(float2*)&out[LOC_OFF + (size_t)p2 * 48 + col] =
                make_float2(acc[nt][2] + b2.x, acc[nt][3] + b2.y);
        } else {
            const int cc2 = col - 48;
            float2 b2 = *(const float2*)&score_b[cc2];
            *(float2*)&out[CLS_OFF + (size_t)p1 * 24 + cc2] =
                make_float2(acc[nt][0] + b2.x, acc[nt][1] + b2.y);
            *(float2*)&out[CLS_OFF + (size_t)p2 * 24 + cc2] =
                make_float2(acc[nt][2] + b2.x, acc[nt][3] + b2.y);
        }
    }
}

// ---------------------------------------------------------------------------
// roi decode (anchor quirk: xi = p>>7, yi = p&127 — x varies slowly)
// ---------------------------------------------------------------------------
__global__ void roi_kernel(float* __restrict__ out){
    int i = blockIdx.x * 256 + threadIdx.x;
    if (i >= HWSZ * NANCH) return;
    int p = i / NANCH, a = i % NANCH;
    float gx = (float)((p >> 7) * 16);
    float gy = (float)((p & 127) * 16);
    const float RAT[3] = {0.5f, 1.0f, 2.0f};
    const float SIZ[4] = {64.f, 128.f, 256.f, 512.f};
    float r = RAT[a >> 2], s = SIZ[a & 3];
    float hr = sqrtf(r);
    float aw = rintf(0.5f * ((1.0f / hr) * s));
    float ah = rintf(0.5f * (hr * s));
    float4 l = *(const float4*)&out[LOC_OFF + (size_t)i * 4];
    float4 ro;
    ro.x = l.x * aw + gx;
    ro.y = l.y * ah + gy;
    ro.z = expf(l.z) * aw;
    ro.w = expf(l.w) * ah;
    *(float4*)&out[ROI_OFF + (size_t)i * 4] = ro;
}

// ---------------------------------------------------------------------------
extern "C" void kernel_launch(void* const* d_in, const int* in_sizes, int n_in,
                              void* d_out, int out_size){
    const float* x       = (const float*)d_in[0];
    const float* conv1_w = (const float*)d_in[1];
    const float* conv1_b = (const float*)d_in[2];
    const float* score_w = (const float*)d_in[3];
    const float* score_b = (const float*)d_in[4];
    const float* loc_w   = (const float*)d_in[5];
    const float* loc_b   = (const float*)d_in[6];
    float* out = (float*)d_out;

    cudaFuncSetAttribute(conv_mma_kernel,
        cudaFuncAttributeMaxDynamicSharedMemorySize, CDYN);
    cudaFuncSetAttribute(head_mma_kernel,
        cudaFuncAttributeMaxDynamicSharedMemorySize, HDYN);

    prep_x_kernel<<<dim3(HWSZ / 32, CC / 32), dim3(32, 8)>>>(x);
    prep_w_kernel<<<(9 * CC * CC + 255) / 256, 256>>>(conv1_w);
    prep_hw_kernel<<<(8 * 72 * 64 + 255) / 256, 256>>>(loc_w, score_w);

    conv_mma_kernel<<<dim3(128, 4, 4), 256, CDYN>>>();

    mid_epilogue_kernel<<<(HWSZ * CC / 4) / 256, 256>>>(conv1_b);

    head_mma_kernel<<<128, 256, HDYN>>>(loc_b, score_b, out);

    roi_kernel<<<(HWSZ * NANCH + 255) / 256, 256>>>(out);
}

// round 7
// speedup vs baseline: 10.7913x; 1.5471x over previous
#include <cuda_runtime.h>
#include <cuda_fp16.h>

#define HH 128
#define WW 128
#define CC 512
#define HWSZ (HH*WW)
#define NANCH 12

#define LOC_OFF   0
#define CLS_OFF   786432
#define ROI_OFF   1179648

// ---------------------------------------------------------------------------
// Global scratch (allocation-free)
// ---------------------------------------------------------------------------
__device__ __align__(256) __half g_xhi[HWSZ * CC];        // x NHWC fp16
__device__ __align__(256) __half g_wh [9 * CC * CC];      // conv W [tap][oc][ic]
__device__ __align__(256) float  g_part[4][HWSZ * CC];    // K-split partials
__device__ __align__(256) __half g_mhi[HWSZ * CC];        // mid NHWC hi
__device__ __align__(256) __half g_mlo[HWSZ * CC];        // mid NHWC lo
__device__ __align__(256) __half g_hw [8 * 72 * 64];      // head W [kc][row72][64]

// ---------------------------------------------------------------------------
// Helpers (plain sm_80+ PTX, legal on the non-'a' compute_103 target)
// ---------------------------------------------------------------------------
__device__ __forceinline__ unsigned smem_u32(const void* p){
    unsigned a;
    asm("{ .reg .u64 t; cvta.to.shared.u64 t, %1; cvt.u32.u64 %0, t; }" : "=r"(a) : "l"(p));
    return a;
}
#define SWZ(b) ((unsigned)(b) ^ ((((unsigned)(b)) >> 3) & 0x70u))

__device__ __forceinline__ void cp16(unsigned dst, const void* src, unsigned sz){
    asm volatile("cp.async.cg.shared.global [%0], [%1], 16, %2;"
        :: "r"(dst), "l"(src), "r"(sz) : "memory");
}
#define CP_COMMIT() asm volatile("cp.async.commit_group;" ::: "memory")
#define CP_WAIT(n)  asm volatile("cp.async.wait_group %0;" :: "n"(n) : "memory")

__device__ __forceinline__ void ldm4(unsigned* r, unsigned addr){
    asm volatile("ldmatrix.sync.aligned.m8n8.x4.shared.b16 {%0,%1,%2,%3}, [%4];"
        : "=r"(r[0]), "=r"(r[1]), "=r"(r[2]), "=r"(r[3]) : "r"(addr));
}
__device__ __forceinline__ void ldm2(unsigned* r, unsigned addr){
    asm volatile("ldmatrix.sync.aligned.m8n8.x2.shared.b16 {%0,%1}, [%2];"
        : "=r"(r[0]), "=r"(r[1]) : "r"(addr));
}
__device__ __forceinline__ void mma16816(float* d, const unsigned* a, const unsigned* b){
    asm volatile("mma.sync.aligned.m16n8k16.row.col.f32.f16.f16.f32 "
        "{%0,%1,%2,%3}, {%4,%5,%6,%7}, {%8,%9}, {%0,%1,%2,%3};"
        : "+f"(d[0]), "+f"(d[1]), "+f"(d[2]), "+f"(d[3])
        : "r"(a[0]), "r"(a[1]), "r"(a[2]), "r"(a[3]), "r"(b[0]), "r"(b[1]));
}

// ---------------------------------------------------------------------------
// Prep kernels
// ---------------------------------------------------------------------------
__global__ void prep_x_kernel(const float* __restrict__ x){
    __shared__ float tile[32][33];
    int hw0 = blockIdx.x * 32, c0 = blockIdx.y * 32;
    int tx = threadIdx.x, ty = threadIdx.y;
    #pragma unroll
    for (int i = 0; i < 32; i += 8)
        tile[ty + i][tx] = x[(size_t)(c0 + ty + i) * HWSZ + hw0 + tx];
    __syncthreads();
    #pragma unroll
    for (int i = 0; i < 32; i += 8){
        int hw = ty + i;
        g_xhi[(size_t)(hw0 + hw) * CC + c0 + tx] = __float2half(tile[tx][hw]);
    }
}

__global__ void prep_w_kernel(const float* __restrict__ w){
    int idx = blockIdx.x * 256 + threadIdx.x;
    if (idx >= 9 * CC * CC) return;
    int tap = idx / (CC * CC);
    int rem = idx % (CC * CC);
    int oc  = rem >> 9;
    int ic  = rem & 511;
    g_wh[idx] = __float2half(w[(size_t)oc * (CC * 9) + ic * 9 + tap]);
}

__global__ void prep_hw_kernel(const float* __restrict__ loc_w,
                               const float* __restrict__ score_w){
    int idx = blockIdx.x * 256 + threadIdx.x;
    if (idx >= 8 * 72 * 64) return;
    int kc  = idx / (72 * 64);
    int rem = idx % (72 * 64);
    int row = rem >> 6;
    int k   = rem & 63;
    float v = (row < 48) ? loc_w[row * CC + kc * 64 + k]
                         : score_w[(row - 48) * CC + kc * 64 + k];
    g_hw[idx] = __float2half(v);
}

// ---------------------------------------------------------------------------
// Conv 3x3, single-pass fp16, K-split x4. grid (128, 4, 4) = 2048 CTAs, 256 thr.
// CTA: M=128 x N=128 x 18 chunks of 64 ic. 8 warps, warp tile 32x64.
// Stage = Ah16K + B16K = 32KB, 3 stages = 96KB -> 2 CTAs/SM.
// ---------------------------------------------------------------------------
#define CSTG  32768
#define CDYN  (3*CSTG)

__device__ __forceinline__ void conv_load_chunk(unsigned sb, int ci, int s,
                                                int y, int oc0, int tid){
    const int tap = ci >> 3;
    const int ic0 = (ci & 7) << 6;
    const int dy = tap / 3 - 1, dx = tap % 3 - 1;
    const int yy = y + dy;
    const bool rowok = ((unsigned)yy < 128u);
    const unsigned stg = sb + s * CSTG;
    #pragma unroll
    for (int j = 0; j < 8; j++){
        int id = tid + j * 256;
        if (id < 1024){                       // A (16KB)
            int row = id >> 3, c = id & 7;
            unsigned dst = stg + SWZ(row * 128 + c * 16);
            int wx = row + dx;
            bool ok = rowok && ((unsigned)wx < 128u);
            const __half* src = g_xhi +
                (ok ? ((size_t)(yy * 128 + wx) * CC + ic0 + c * 8) : 0);
            cp16(dst, src, ok ? 16u : 0u);
        } else {                              // B (16KB)
            int idb = id - 1024;
            int row = idb >> 3, c = idb & 7;
            unsigned dst = stg + 16384 + SWZ(row * 128 + c * 16);
            cp16(dst, g_wh + (size_t)tap * (CC * CC)
                     + (size_t)(oc0 + row) * CC + ic0 + c * 8, 16u);
        }
    }
}

__global__ void __launch_bounds__(256, 2) conv_mma_kernel(){
    extern __shared__ __align__(1024) char dsm[];
    const unsigned sb = smem_u32(dsm);
    const int tid = threadIdx.x, lane = tid & 31, wid = tid >> 5;
    const int y = blockIdx.x, oc0 = blockIdx.y * 128, ks = blockIdx.z;
    const int cbase = ks * 18;
    const int m0 = (wid & 3) * 32, n0 = (wid >> 2) * 64;

    float acc[2][8][4];
    #pragma unroll
    for (int a = 0; a < 2; a++)
        #pragma unroll
        for (int b = 0; b < 8; b++)
            #pragma unroll
            for (int c = 0; c < 4; c++) acc[a][b][c] = 0.f;

    const int a_row = lane & 15;
    const int a_kad = (lane >> 4) << 4;
    const int b_row = ((lane >> 4) << 3) + (lane & 7);
    const int b_kad = ((lane >> 3) & 1) << 4;

    conv_load_chunk(sb, cbase + 0, 0, y, oc0, tid); CP_COMMIT();
    conv_load_chunk(sb, cbase + 1, 1, y, oc0, tid); CP_COMMIT();
    conv_load_chunk(sb, cbase + 2, 2, y, oc0, tid); CP_COMMIT();

    int s = 0;
    for (int i = 0; i < 18; i++){
        if (i <= 15)      CP_WAIT(2);
        else if (i == 16) CP_WAIT(1);
        else              CP_WAIT(0);
        __syncthreads();

        const unsigned Ah = sb + s * CSTG;
        const unsigned Bh = Ah + 16384;

        #pragma unroll
        for (int k16 = 0; k16 < 4; k16++){
            const int koff = k16 * 32;
            unsigned ah[2][4];
            #pragma unroll
            for (int mt = 0; mt < 2; mt++)
                ldm4(ah[mt], Ah + SWZ((m0 + mt * 16 + a_row) * 128 + koff + a_kad));
            unsigned bh[4][4];
            #pragma unroll
            for (int bt = 0; bt < 4; bt++)
                ldm4(bh[bt], Bh + SWZ((n0 + bt * 16 + b_row) * 128 + koff + b_kad));
            #pragma unroll
            for (int mt = 0; mt < 2; mt++)
                #pragma unroll
                for (int bt = 0; bt < 4; bt++){
                    mma16816(acc[mt][2*bt],   ah[mt], &bh[bt][0]);
                    mma16816(acc[mt][2*bt+1], ah[mt], &bh[bt][2]);
                }
        }
        __syncthreads();   // all warps done with stage s before refilling it

        if (i + 3 < 18){
            conv_load_chunk(sb, cbase + i + 3, s, y, oc0, tid);
            CP_COMMIT();
        }
        s = (s == 2) ? 0 : s + 1;
    }

    // Store raw fp32 partials
    float* pb = g_part[ks];
    const int er = lane >> 2;
    const int ec = (lane & 3) * 2;
    #pragma unroll
    for (int mt = 0; mt < 2; mt++){
        #pragma unroll
        for (int nt = 0; nt < 8; nt++){
            const int oc = oc0 + n0 + nt * 8 + ec;
            #pragma unroll
            for (int h = 0; h < 2; h++){
                const size_t p = (size_t)y * 128 + m0 + mt * 16 + er + h * 8;
                *(float2*)&pb[p * CC + oc] =
                    make_float2(acc[mt][nt][2*h+0], acc[mt][nt][2*h+1]);
            }
        }
    }
}

// ---------------------------------------------------------------------------
// Epilogue: sum 4 partials + bias + relu, split fp16 hi/lo -> g_mhi/g_mlo
// ---------------------------------------------------------------------------
__global__ void __launch_bounds__(256) mid_epilogue_kernel(const float* __restrict__ bias){
    const size_t i4 = ((size_t)blockIdx.x * 256 + threadIdx.x) * 4;
    const int oc = (int)(i4 & 511);
    float4 s0 = *(const float4*)&g_part[0][i4];
    float4 s1 = *(const float4*)&g_part[1][i4];
    float4 s2 = *(const float4*)&g_part[2][i4];
    float4 s3 = *(const float4*)&g_part[3][i4];
    float4 b4 = *(const float4*)&bias[oc];
    float v0 = fmaxf(s0.x + s1.x + s2.x + s3.x + b4.x, 0.f);
    float v1 = fmaxf(s0.y + s1.y + s2.y + s3.y + b4.y, 0.f);
    float v2 = fmaxf(s0.z + s1.z + s2.z + s3.z + b4.z, 0.f);
    float v3 = fmaxf(s0.w + s1.w + s2.w + s3.w + b4.w, 0.f);
    __half h0 = __float2half(v0), h1 = __float2half(v1);
    __half h2 = __float2half(v2), h3 = __float2half(v3);
    __half l0 = __float2half(v0 - __half2float(h0));
    __half l1 = __float2half(v1 - __half2float(h1));
    __half l2 = __float2half(v2 - __half2float(h2));
    __half l3 = __float2half(v3 - __half2float(h3));
    uint2 hp = make_uint2((unsigned)*(unsigned short*)&h0 | ((unsigned)*(unsigned short*)&h1 << 16),
                          (unsigned)*(unsigned short*)&h2 | ((unsigned)*(unsigned short*)&h3 << 16));
    uint2 lp = make_uint2((unsigned)*(unsigned short*)&l0 | ((unsigned)*(unsigned short*)&l1 << 16),
                          (unsigned)*(unsigned short*)&l2 | ((unsigned)*(unsigned short*)&l3 << 16));
    *(uint2*)&g_mhi[i4] = hp;
    *(uint2*)&g_mlo[i4] = lp;
}

// ---------------------------------------------------------------------------
// Head GEMM: M=128/CTA (grid 128), N=72, K=512. 2-pass fp16 (mid hi/lo).
// ---------------------------------------------------------------------------
#define HB    73728
#define HASTG 32768
#define HDYN  (HB + 2*HASTG)

__device__ __forceinline__ void head_load_A(unsigned sb, int i, int s,
                                            int p0, int tid){
    const unsigned ast = sb + HB + s * HASTG;
    const int ic0 = i * 64;
    #pragma unroll
    for (int j = 0; j < 8; j++){
        int id = tid + j * 256;
        int part = id >> 10, rem = id & 1023;
        int row = rem >> 3, c = rem & 7;
        unsigned dst = ast + part * 16384 + SWZ(row * 128 + c * 16);
        const __half* base = part ? g_mlo : g_mhi;
        cp16(dst, base + (size_t)(p0 + row) * CC + ic0 + c * 8, 16u);
    }
}

__global__ void __launch_bounds__(256, 1) head_mma_kernel(
        const float* __restrict__ loc_b, const float* __restrict__ score_b,
        float* __restrict__ out){
    extern __shared__ __align__(1024) char dsm[];
    const unsigned sb = smem_u32(dsm);
    const int tid = threadIdx.x, lane = tid & 31, wid = tid >> 5;
    const int p0 = blockIdx.x * 128;
    const int m0 = wid * 16;

    float acc[9][4];
    #pragma unroll
    for (int n = 0; n < 9; n++)
        #pragma unroll
        for (int c = 0; c < 4; c++) acc[n][c] = 0.f;

    #pragma unroll
    for (int j = 0; j < 18; j++){
        int id = tid + j * 256;
        int kc  = id / 576;
        int rem = id % 576;
        int row = rem >> 3, c = rem & 7;
        unsigned dst = sb + kc * 9216 + SWZ(row * 128 + c * 16);
        cp16(dst, g_hw + kc * 4608 + row * 64 + c * 8, 16u);
    }
    head_load_A(sb, 0, 0, p0, tid);
    CP_COMMIT();

    const int a_row = lane & 15;
    const int a_kad = (lane >> 4) << 4;
    const int b_row = lane & 7;
    const int b_kad = ((lane >> 3) & 1) << 4;

    for (int i = 0; i < 8; i++){
        const int s = i & 1;
        if (i < 7){
            head_load_A(sb, i + 1, (i + 1) & 1, p0, tid);
            CP_COMMIT();
            CP_WAIT(1);
        } else {
            CP_WAIT(0);
        }
        __syncthreads();

        const unsigned Ah = sb + HB + s * HASTG;
        const unsigned Al = Ah + 16384;
        const unsigned Bh = sb + i * 9216;

        #pragma unroll
        for (int k16 = 0; k16 < 4; k16++){
            const int koff = k16 * 32;
            unsigned ah[4], al[4];
            {
                unsigned off = SWZ((m0 + a_row) * 128 + koff + a_kad);
                ldm4(ah, Ah + off);
                ldm4(al, Al + off);
            }
            #pragma unroll
            for (int nt = 0; nt < 9; nt++){
                unsigned off = SWZ((nt * 8 + b_row) * 128 + koff + b_kad);
                unsigned bh2[2];
                ldm2(bh2, Bh + off);
                mma16816(acc[nt], ah, bh2);
                mma16816(acc[nt], al, bh2);
            }
        }
        __syncthreads();
    }

    const int er = lane >> 2;
    const int ec = (lane & 3) * 2;
    #pragma unroll
    for (int nt = 0; nt < 9; nt++){
        const int col = nt * 8 + ec;
        const int p1 = p0 + m0 + er;
        const int p2 = p1 + 8;
        if (col < 48){
            float2 b2 = *(const float2*)&loc_b[col];
            *(float2*)&out[LOC_OFF + (size_t)p1 * 48 + col] =
                make_float2(acc[nt][0] + b2.x, acc[nt][1] + b2.y);
            *(float2*)&out[LOC_OFF + (size_t)p2 * 48 + col] =
                make_float2(acc[nt][2] + b2.x, acc[nt][3] + b2.y);
        } else {
            const int cc2 = col - 48;
            float2 b2 = *(const float2*)&score_b[cc2];
            *(float2*)&out[CLS_OFF + (size_t)p1 * 24 + cc2] =
                make_float2(acc[nt][0] + b2.x, acc[nt][1] + b2.y);
            *(float2*)&out[CLS_OFF + (size_t)p2 * 24 + cc2] =
                make_float2(acc[nt][2] + b2.x, acc[nt][3] + b2.y);
        }
    }
}

// ---------------------------------------------------------------------------
// roi decode (anchor quirk: xi = p>>7, yi = p&127 — x varies slowly)
// ---------------------------------------------------------------------------
__global__ void roi_kernel(float* __restrict__ out){
    int i = blockIdx.x * 256 + threadIdx.x;
    if (i >= HWSZ * NANCH) return;
    int p = i / NANCH, a = i % NANCH;
    float gx = (float)((p >> 7) * 16);
    float gy = (float)((p & 127) * 16);
    const float RAT[3] = {0.5f, 1.0f, 2.0f};
    const float SIZ[4] = {64.f, 128.f, 256.f, 512.f};
    float r = RAT[a >> 2], s = SIZ[a & 3];
    float hr = sqrtf(r);
    float aw = rintf(0.5f * ((1.0f / hr) * s));
    float ah = rintf(0.5f * (hr * s));
    float4 l = *(const float4*)&out[LOC_OFF + (size_t)i * 4];
    float4 ro;
    ro.x = l.x * aw + gx;
    ro.y = l.y * ah + gy;
    ro.z = expf(l.z) * aw;
    ro.w = expf(l.w) * ah;
    *(float4*)&out[ROI_OFF + (size_t)i * 4] = ro;
}

// ---------------------------------------------------------------------------
extern "C" void kernel_launch(void* const* d_in, const int* in_sizes, int n_in,
                              void* d_out, int out_size){
    const float* x       = (const float*)d_in[0];
    const float* conv1_w = (const float*)d_in[1];
    const float* conv1_b = (const float*)d_in[2];
    const float* score_w = (const float*)d_in[3];
    const float* score_b = (const float*)d_in[4];
    const float* loc_w   = (const float*)d_in[5];
    const float* loc_b   = (const float*)d_in[6];
    float* out = (float*)d_out;

    cudaFuncSetAttribute(conv_mma_kernel,
        cudaFuncAttributeMaxDynamicSharedMemorySize, CDYN);
    cudaFuncSetAttribute(head_mma_kernel,
        cudaFuncAttributeMaxDynamicSharedMemorySize, HDYN);

    prep_x_kernel<<<dim3(HWSZ / 32, CC / 32), dim3(32, 8)>>>(x);
    prep_w_kernel<<<(9 * CC * CC + 255) / 256, 256>>>(conv1_w);
    prep_hw_kernel<<<(8 * 72 * 64 + 255) / 256, 256>>>(loc_w, score_w);

    conv_mma_kernel<<<dim3(128, 4, 4), 256, CDYN>>>();

    mid_epilogue_kernel<<<(HWSZ * CC / 4) / 256, 256>>>(conv1_b);

    head_mma_kernel<<<128, 256, HDYN>>>(loc_b, score_b, out);

    roi_kernel<<<(HWSZ * NANCH + 255) / 256, 256>>>(out);
}